// round 8
// baseline (speedup 1.0000x reference)
#include <cuda_runtime.h>
#include <cstdint>

// ---------------------------------------------------------------------------
// HODLR linear, f32x2-packed version.
//
// Kernel 1 (proj): T[tok][l][b][r] = sum_k x[tok][k]*us[l][k][r], all 6 layers
//   fused in one k-sweep. Inner product packed over k-parity via fma.rn.f32x2;
//   weights re-staged interleaved (k/2, r, k&1) so B-pairs are natural LDS.64.
// Kernel 2 (expand): per output fine block j: single K=160 register GEMM
//   (64 diag k + 96 low-rank coeffs) with A = [x_block | T_slices] unified in
//   one smem buffer and B = [ds_j | vs slices] interleaved as k-pairs.
// ---------------------------------------------------------------------------

#define NTHREADS 256

__device__ __align__(16) float g_T[16384ull * 2048];

struct Ptr6 { const float* p[6]; };

__host__ __device__ __forceinline__ int t_off(int l) {
    const int offs[6] = {0, 32, 96, 224, 480, 992};
    return offs[l];
}

typedef unsigned long long u64;

__device__ __forceinline__ void ffma2(u64& d, u64 a, u64 b) {
    asm("fma.rn.f32x2 %0, %1, %2, %0;" : "+l"(d) : "l"(a), "l"(b));
}
__device__ __forceinline__ float hadd2(u64 v) {
    float lo, hi;
    asm("mov.b64 {%0, %1}, %2;" : "=f"(lo), "=f"(hi) : "l"(v));
    return lo + hi;
}

// ===========================================================================
// Kernel 1: U projections (6 layers fused), k-parity packed FFMA2.
// Grid: 256 CTAs x 256 thr. Thread (tg=tid>>4, cg=tid&15): 4 tokens, rank cg.
// ===========================================================================
__global__ __launch_bounds__(NTHREADS) void hodlr_proj_kernel(
    const float* __restrict__ x, Ptr6 us)
{
    __shared__ float xs[64 * 68];        // 64 tok x 64 k (pad 68)
    __shared__ float wsp[6 * 1024];      // [l][k/2][r][2] interleaved k-pairs

    const int tid  = threadIdx.x;
    const int tg   = tid >> 4;
    const int cg   = tid & 15;
    const int tok0 = blockIdx.x * 64;

    u64 acc2[4][6];
#pragma unroll
    for (int e = 0; e < 4; e++)
#pragma unroll
        for (int l = 0; l < 6; l++) acc2[e][l] = 0ull;

    for (int kc = 0; kc < 64; kc++) {
        // ---- stage x tile ----
        {
            const int row = tid >> 4, f4c = tid & 15;
#pragma unroll
            for (int p = 0; p < 4; p++) {
                const int r = row + p * 16;
                float4 v = *reinterpret_cast<const float4*>(
                    x + (size_t)(tok0 + r) * 4096 + kc * 64 + f4c * 4);
                *reinterpret_cast<float4*>(xs + r * 68 + f4c * 4) = v;
            }
        }
        // ---- stage weights interleaved: wsp[l][(k>>1)*32 + r*2 + (k&1)] ----
#pragma unroll
        for (int p = 0; p < 6; p++) {
            const int idx = p * 256 + tid;        // 1536 float4
            const int l = idx >> 8, f4i = idx & 255;
            const int k = f4i >> 2, rq = f4i & 3;
            float4 v = *reinterpret_cast<const float4*>(
                us.p[l] + (size_t)kc * 1024 + f4i * 4);
            float* dst = wsp + l * 1024 + (k >> 1) * 32 + (k & 1);
            dst[(rq * 4 + 0) * 2] = v.x;
            dst[(rq * 4 + 1) * 2] = v.y;
            dst[(rq * 4 + 2) * 2] = v.z;
            dst[(rq * 4 + 3) * 2] = v.w;
        }
        __syncthreads();

        // ---- packed accumulate ----
#pragma unroll 4
        for (int kk = 0; kk < 64; kk += 4) {
            ulonglong2 ap[4];
#pragma unroll
            for (int e = 0; e < 4; e++)
                ap[e] = *reinterpret_cast<const ulonglong2*>(
                    xs + (tg * 4 + e) * 68 + kk);
#pragma unroll
            for (int qp = 0; qp < 2; qp++) {
                u64 wv[6];
#pragma unroll
                for (int l = 0; l < 6; l++)
                    wv[l] = *reinterpret_cast<const u64*>(
                        wsp + l * 1024 + ((kk >> 1) + qp) * 32 + cg * 2);
#pragma unroll
                for (int e = 0; e < 4; e++) {
                    const u64 a = qp ? ap[e].y : ap[e].x;
#pragma unroll
                    for (int l = 0; l < 6; l++)
                        ffma2(acc2[e][l], a, wv[l]);
                }
            }
        }
        __syncthreads();

        // ---- flush layers whose block ends here (always even k) ----
#pragma unroll
        for (int l = 0; l < 6; l++) {
            const int mask = (1 << (5 - l)) - 1;
            if (((kc + 1) & mask) == 0) {
                const int b = kc >> (5 - l);
#pragma unroll
                for (int e = 0; e < 4; e++) {
                    g_T[(size_t)(tok0 + tg * 4 + e) * 2048 + t_off(l) + b * 16 + cg]
                        = hadd2(acc2[e][l]);
                    acc2[e][l] = 0ull;
                }
            }
        }
    }
}

// ===========================================================================
// Kernel 2: unified K=160 expansion per output block, k-parity packed FFMA2.
// Grid: (64 blocks, 256 token tiles) x 256 thr. Thread: 4 tok x 4 col.
// smem: as[64][164] (A = x|T per token) + wp[80][64][2] (B k-pair interleave)
//       = 82944 B dynamic.
// ===========================================================================
__global__ __launch_bounds__(NTHREADS, 2) void hodlr_expand_kernel(
    const float* __restrict__ x, Ptr6 vs, const float* __restrict__ ds,
    const float* __restrict__ bias, float* __restrict__ out)
{
    extern __shared__ float sm[];
    float* as = sm;             // [64 tok][164] : cols 0..63 x, 64..159 T
    float* wp = sm + 64 * 164;  // [80 kpair][64 col][2]

    const int tid  = threadIdx.x;
    const int j    = blockIdx.x;
    const int tok0 = blockIdx.y * 64;
    const int tg   = tid >> 4;
    const int colg = tid & 15;

    int pb[6], lo[6];
#pragma unroll
    for (int l = 0; l < 6; l++) {
        const int shift = 5 - l;
        pb[l] = (j >> shift) ^ 1;
        lo[l] = (j & ((1 << shift) - 1)) * 64;
    }

    // ---- stage x block j -> as[:, 0..63] ----
    {
        const int row = tid >> 4, f4c = tid & 15;
#pragma unroll
        for (int p = 0; p < 4; p++) {
            const int r = row + p * 16;
            float4 v = *reinterpret_cast<const float4*>(
                x + (size_t)(tok0 + r) * 4096 + j * 64 + f4c * 4);
            *reinterpret_cast<float4*>(as + r * 164 + f4c * 4) = v;
        }
    }
    // ---- stage T slices -> as[:, 64..159] ----
#pragma unroll
    for (int p = 0; p < 6; p++) {
        const int idx = p * 256 + tid;            // 1536 float4
        const int tok = idx / 24, c4 = idx % 24;
        const int c = c4 * 4, l = c >> 4, r = c & 15;
        float4 v = *reinterpret_cast<const float4*>(
            &g_T[(size_t)(tok0 + tok) * 2048 + t_off(l) + pb[l] * 16 + r]);
        *reinterpret_cast<float4*>(as + tok * 164 + 64 + c) = v;
    }
    // ---- stage ds[j] interleaved -> wp rows 0..31 ----
#pragma unroll
    for (int p = 0; p < 4; p++) {
        const int f4i = p * 256 + tid;            // 1024 float4
        const int k = f4i >> 4, colq = f4i & 15;
        float4 v = *reinterpret_cast<const float4*>(ds + (size_t)j * 4096 + f4i * 4);
        float* dst = wp + (k >> 1) * 128 + (k & 1);
        dst[(colq * 4 + 0) * 2] = v.x;
        dst[(colq * 4 + 1) * 2] = v.y;
        dst[(colq * 4 + 2) * 2] = v.z;
        dst[(colq * 4 + 3) * 2] = v.w;
    }
    // ---- stage vs slices interleaved -> wp rows 32..79 ----
#pragma unroll
    for (int p = 0; p < 6; p++) {
        const int idx = p * 256 + tid;            // 1536 float4
        const int c = idx >> 4, f4 = idx & 15;    // c = l*16+r in 0..95
        const int l = c >> 4, r = c & 15;
        const int cl = 1 << (11 - l);
        float4 v = *reinterpret_cast<const float4*>(
            vs.p[l] + (size_t)(pb[l] * 16 + r) * cl + lo[l] + f4 * 4);
        float* dst = wp + (32 + (c >> 1)) * 128 + (c & 1);
        dst[(f4 * 4 + 0) * 2] = v.x;
        dst[(f4 * 4 + 1) * 2] = v.y;
        dst[(f4 * 4 + 2) * 2] = v.z;
        dst[(f4 * 4 + 3) * 2] = v.w;
    }
    __syncthreads();

    u64 acc2[4][4];
#pragma unroll
    for (int e = 0; e < 4; e++)
#pragma unroll
        for (int c = 0; c < 4; c++) acc2[e][c] = 0ull;

    // ---- unified K=160 packed GEMM ----
#pragma unroll 4
    for (int kk = 0; kk < 160; kk += 4) {
        ulonglong2 ap[4];
#pragma unroll
        for (int e = 0; e < 4; e++)
            ap[e] = *reinterpret_cast<const ulonglong2*>(
                as + (tg * 4 + e) * 164 + kk);
#pragma unroll
        for (int qp = 0; qp < 2; qp++) {
            u64 bv[4];
#pragma unroll
            for (int c = 0; c < 4; c++)
                bv[c] = *reinterpret_cast<const u64*>(
                    wp + ((kk >> 1) + qp) * 128 + (colg * 4 + c) * 2);
#pragma unroll
            for (int e = 0; e < 4; e++) {
                const u64 a = qp ? ap[e].y : ap[e].x;
#pragma unroll
                for (int c = 0; c < 4; c++)
                    ffma2(acc2[e][c], a, bv[c]);
            }
        }
    }

    // ---- horizontal add + bias + store ----
    float4 bv = *reinterpret_cast<const float4*>(bias + j * 64 + colg * 4);
#pragma unroll
    for (int e = 0; e < 4; e++) {
        float4 o;
        o.x = hadd2(acc2[e][0]) + bv.x;
        o.y = hadd2(acc2[e][1]) + bv.y;
        o.z = hadd2(acc2[e][2]) + bv.z;
        o.w = hadd2(acc2[e][3]) + bv.w;
        *reinterpret_cast<float4*>(
            out + (size_t)(tok0 + tg * 4 + e) * 4096 + j * 64 + colg * 4) = o;
    }
}

// ===========================================================================
// Launch
// ===========================================================================
extern "C" void kernel_launch(void* const* d_in, const int* in_sizes, int n_in,
                              void* d_out, int out_size)
{
    (void)in_sizes; (void)n_in; (void)out_size;

    const float* x    = (const float*)d_in[0];
    Ptr6 us, vs;
    for (int l = 0; l < 6; l++) {
        us.p[l] = (const float*)d_in[1 + 2 * l];
        vs.p[l] = (const float*)d_in[2 + 2 * l];
    }
    const float* ds   = (const float*)d_in[13];
    const float* bias = (const float*)d_in[14];
    float* out        = (float*)d_out;

    const int SMEM2 = (64 * 164 + 80 * 128) * (int)sizeof(float);  // 82944 B
    cudaFuncSetAttribute(hodlr_expand_kernel,
                         cudaFuncAttributeMaxDynamicSharedMemorySize, SMEM2);

    hodlr_proj_kernel<<<256, NTHREADS>>>(x, us);
    hodlr_expand_kernel<<<dim3(64, 256), NTHREADS, SMEM2>>>(x, vs, ds, bias, out);
}

// round 10
// speedup vs baseline: 1.2474x; 1.2474x over previous
#include <cuda_runtime.h>
#include <cstdint>

// ---------------------------------------------------------------------------
// HODLR linear, f32x2-packed, conflict-free, repacked-weight version.
//
// Pipeline per launch:
//   repack kernels: us -> g_Wp, ds -> g_Dp, vs -> g_Vp (k-pair interleaved)
//   proj:   T[tok][l][b][r] = sum_k x[tok][k] us[l][k][r]  (6 layers fused,
//           FFMA2 over k-parity, reg-prefetch double buffering)
//   expand: per output fine block j, K=160 packed GEMM
//           A=[x_j | T slices], B=[ds_j | vs slices], + bias.
//           Thread colg owns cols {colg, colg+16, colg+32, colg+48} so the
//           B LDS.64 hits bank 2*colg per lane -> conflict-free.
// ---------------------------------------------------------------------------

#define NTHREADS 256

__device__ __align__(16) float g_T[16384ull * 2048];
// us repacked: [kc(64)][l(6)][kpair(32)][r(16)][par(2)]  (6144 floats per kc)
__device__ __align__(16) float g_Wp[64 * 6144];
// ds repacked: [j(64)][kpair(32)][col(64)][par(2)]
__device__ __align__(16) float g_Dp[64 * 4096];
// vs repacked: [l] base l*131072, then ((pb*8+rp)*cl + col)*2 + par
__device__ __align__(16) float g_Vp[6 * 131072];

struct Ptr6 { const float* p[6]; };

__host__ __device__ __forceinline__ int t_off(int l) {
    const int offs[6] = {0, 32, 96, 224, 480, 992};
    return offs[l];
}

typedef unsigned long long u64;

__device__ __forceinline__ void ffma2(u64& d, u64 a, u64 b) {
    asm("fma.rn.f32x2 %0, %1, %2, %0;" : "+l"(d) : "l"(a), "l"(b));
}
__device__ __forceinline__ float hadd2(u64 v) {
    float lo, hi;
    asm("mov.b64 {%0, %1}, %2;" : "=f"(lo), "=f"(hi) : "l"(v));
    return lo + hi;
}

// ===========================================================================
// Repack kernels (run once per launch; tiny)
// ===========================================================================
__global__ void repack_us_kernel(Ptr6 us)
{
    const int i = blockIdx.x * blockDim.x + threadIdx.x;   // 24576 threads
    if (i >= 6 * 4096) return;
    const int l = i >> 12, k = i & 4095;
    const int kc = k >> 6, kp = (k & 63) >> 1, par = k & 1;
    const float* src = us.p[l] + (size_t)k * 16;
    float* dst = g_Wp + kc * 6144 + l * 1024 + kp * 32 + par;
#pragma unroll
    for (int r = 0; r < 16; r++) dst[r * 2] = src[r];
}

__global__ void repack_ds_kernel(const float* __restrict__ ds)
{
    const int i = blockIdx.x * blockDim.x + threadIdx.x;   // 4096 threads
    if (i >= 64 * 64) return;
    const int j = i >> 6, k = i & 63;
    const float* src = ds + (size_t)j * 4096 + k * 64;
    float* dst = g_Dp + j * 4096 + (k >> 1) * 128 + (k & 1);
#pragma unroll
    for (int c = 0; c < 64; c++) dst[c * 2] = src[c];
}

__global__ void repack_vs_kernel(Ptr6 vs)
{
    // one thread per 4 source cols; 6 layers x 131072/4 = 196608 threads
    const int i = blockIdx.x * blockDim.x + threadIdx.x;
    if (i >= 6 * 32768) return;
    const int l = i / 32768, e4 = i % 32768;
    const int s = e4 * 4;                 // source flat idx within layer
    const int cl = 1 << (11 - l);
    const int row = s / cl;               // pb*16 + r
    const int col = s % cl;               // multiple of 4 (cl >= 64)
    const int pb = row >> 4, r = row & 15;
    float4 v = *reinterpret_cast<const float4*>(vs.p[l] + (size_t)s);
    float* dst = g_Vp + l * 131072 +
                 (((pb * 8 + (r >> 1)) * cl + col) * 2 + (r & 1));
    dst[0] = v.x; dst[2] = v.y; dst[4] = v.z; dst[6] = v.w;
}

// ===========================================================================
// Kernel 1: U projections (6 layers fused), FFMA2, reg-prefetch double buffer.
// Grid: 256 CTAs x 256 thr. Thread (tg=tid>>4, cg=tid&15): 4 tokens, rank cg.
// ===========================================================================
__global__ __launch_bounds__(NTHREADS) void hodlr_proj_kernel(
    const float* __restrict__ x)
{
    __shared__ float xs[64 * 68];     // 64 tok x 64 k (pad 68)
    __shared__ float wsp[6 * 1024];   // [l][kpair][r][par]

    const int tid  = threadIdx.x;
    const int tg   = tid >> 4;
    const int cg   = tid & 15;
    const int tok0 = blockIdx.x * 64;
    const int row  = tid >> 4, f4c = tid & 15;

    u64 acc2[4][6];
#pragma unroll
    for (int e = 0; e < 4; e++)
#pragma unroll
        for (int l = 0; l < 6; l++) acc2[e][l] = 0ull;

    float4 xa[4], wa[6];
    // prefetch kc=0
#pragma unroll
    for (int p = 0; p < 4; p++)
        xa[p] = *reinterpret_cast<const float4*>(
            x + (size_t)(tok0 + row + p * 16) * 4096 + f4c * 4);
#pragma unroll
    for (int p = 0; p < 6; p++)
        wa[p] = *reinterpret_cast<const float4*>(
            g_Wp + (p * 256 + tid) * 4);

    for (int kc = 0; kc < 64; kc++) {
        // store staged chunk
#pragma unroll
        for (int p = 0; p < 4; p++)
            *reinterpret_cast<float4*>(xs + (row + p * 16) * 68 + f4c * 4) = xa[p];
#pragma unroll
        for (int p = 0; p < 6; p++)
            *reinterpret_cast<float4*>(wsp + (p * 256 + tid) * 4) = wa[p];
        __syncthreads();

        // prefetch next chunk
        if (kc < 63) {
#pragma unroll
            for (int p = 0; p < 4; p++)
                xa[p] = *reinterpret_cast<const float4*>(
                    x + (size_t)(tok0 + row + p * 16) * 4096
                      + (kc + 1) * 64 + f4c * 4);
#pragma unroll
            for (int p = 0; p < 6; p++)
                wa[p] = *reinterpret_cast<const float4*>(
                    g_Wp + (size_t)(kc + 1) * 6144 + (p * 256 + tid) * 4);
        }

        // packed accumulate
#pragma unroll 4
        for (int kk = 0; kk < 64; kk += 4) {
            ulonglong2 ap[4];
#pragma unroll
            for (int e = 0; e < 4; e++)
                ap[e] = *reinterpret_cast<const ulonglong2*>(
                    xs + (tg * 4 + e) * 68 + kk);
#pragma unroll
            for (int qp = 0; qp < 2; qp++) {
                u64 wv[6];
#pragma unroll
                for (int l = 0; l < 6; l++)
                    wv[l] = *reinterpret_cast<const u64*>(
                        wsp + l * 1024 + ((kk >> 1) + qp) * 32 + cg * 2);
#pragma unroll
                for (int e = 0; e < 4; e++) {
                    const u64 a = qp ? ap[e].y : ap[e].x;
#pragma unroll
                    for (int l = 0; l < 6; l++)
                        ffma2(acc2[e][l], a, wv[l]);
                }
            }
        }
        __syncthreads();

        // flush layers whose block ends here
#pragma unroll
        for (int l = 0; l < 6; l++) {
            const int mask = (1 << (5 - l)) - 1;
            if (((kc + 1) & mask) == 0) {
                const int b = kc >> (5 - l);
#pragma unroll
                for (int e = 0; e < 4; e++) {
                    g_T[(size_t)(tok0 + tg * 4 + e) * 2048 + t_off(l) + b * 16 + cg]
                        = hadd2(acc2[e][l]);
                    acc2[e][l] = 0ull;
                }
            }
        }
    }
}

// ===========================================================================
// Kernel 2: unified K=160 expansion, FFMA2, conflict-free column mapping.
// Grid: (64 j, 256 token tiles) x 256 thr. Thread: 4 tok x cols {colg+16c}.
// smem: as[64][164] + wp[80][128] = 81920+... = (64*164 + 80*128)*4 B
// ===========================================================================
__global__ __launch_bounds__(NTHREADS, 2) void hodlr_expand_kernel(
    const float* __restrict__ x, const float* __restrict__ bias,
    float* __restrict__ out)
{
    extern __shared__ float sm[];
    float* as = sm;             // [64 tok][164] : cols 0..63 x, 64..159 T
    float* wp = sm + 64 * 164;  // [80 kpair][64 col x 2]

    const int tid  = threadIdx.x;
    const int j    = blockIdx.x;
    const int tok0 = blockIdx.y * 64;
    const int tg   = tid >> 4;
    const int colg = tid & 15;

    int pb[6], lo[6];
#pragma unroll
    for (int l = 0; l < 6; l++) {
        const int shift = 5 - l;
        pb[l] = (j >> shift) ^ 1;
        lo[l] = (j & ((1 << shift) - 1)) * 64;
    }

    // ---- stage x block j -> as[:, 0..63] ----
    {
        const int row = tid >> 4, f4c = tid & 15;
#pragma unroll
        for (int p = 0; p < 4; p++) {
            const int r = row + p * 16;
            float4 v = *reinterpret_cast<const float4*>(
                x + (size_t)(tok0 + r) * 4096 + j * 64 + f4c * 4);
            *reinterpret_cast<float4*>(as + r * 164 + f4c * 4) = v;
        }
    }
    // ---- stage T slices -> as[:, 64..159] ----
#pragma unroll
    for (int p = 0; p < 6; p++) {
        const int idx = p * 256 + tid;            // 1536 float4
        const int tok = idx / 24, c4 = idx % 24;
        const int c = c4 * 4, l = c >> 4, r = c & 15;
        float4 v = *reinterpret_cast<const float4*>(
            &g_T[(size_t)(tok0 + tok) * 2048 + t_off(l) + pb[l] * 16 + r]);
        *reinterpret_cast<float4*>(as + tok * 164 + 64 + c) = v;
    }
    // ---- stage ds (pre-interleaved) -> wp rows 0..31 : straight copy ----
#pragma unroll
    for (int p = 0; p < 4; p++) {
        const int f4i = p * 256 + tid;            // 1024 float4
        float4 v = *reinterpret_cast<const float4*>(g_Dp + j * 4096 + f4i * 4);
        *reinterpret_cast<float4*>(wp + f4i * 4) = v;
    }
    // ---- stage vs slices (pre-interleaved) -> wp rows 32..79 ----
#pragma unroll
    for (int p = 0; p < 6; p++) {
        const int idx = p * 256 + tid;            // 1536 float4
        const int rr = idx >> 5, f4 = idx & 31;   // rr = l*8+rp in 0..47
        const int l = rr >> 3, rp = rr & 7;
        const int cl = 1 << (11 - l);
        float4 v = *reinterpret_cast<const float4*>(
            g_Vp + l * 131072 + ((pb[l] * 8 + rp) * cl + lo[l]) * 2 + f4 * 4);
        *reinterpret_cast<float4*>(wp + (32 + rr) * 128 + f4 * 4) = v;
    }
    __syncthreads();

    u64 acc2[4][4];
#pragma unroll
    for (int e = 0; e < 4; e++)
#pragma unroll
        for (int c = 0; c < 4; c++) acc2[e][c] = 0ull;

    // ---- unified K=160 packed GEMM (B: bank 2*colg per lane, no conflict) --
#pragma unroll 4
    for (int kk = 0; kk < 160; kk += 4) {
        ulonglong2 ap[4];
#pragma unroll
        for (int e = 0; e < 4; e++)
            ap[e] = *reinterpret_cast<const ulonglong2*>(
                as + (tg * 4 + e) * 164 + kk);
#pragma unroll
        for (int qp = 0; qp < 2; qp++) {
            u64 bv[4];
#pragma unroll
            for (int c = 0; c < 4; c++)
                bv[c] = *reinterpret_cast<const u64*>(
                    wp + ((kk >> 1) + qp) * 128 + (colg + 16 * c) * 2);
#pragma unroll
            for (int e = 0; e < 4; e++) {
                const u64 a = qp ? ap[e].y : ap[e].x;
#pragma unroll
                for (int c = 0; c < 4; c++)
                    ffma2(acc2[e][c], a, bv[c]);
            }
        }
    }

    // ---- horizontal add + bias + store (cols colg + 16c) ----
    float bvv[4];
#pragma unroll
    for (int c = 0; c < 4; c++) bvv[c] = bias[j * 64 + colg + 16 * c];
#pragma unroll
    for (int e = 0; e < 4; e++) {
        float* orow = out + (size_t)(tok0 + tg * 4 + e) * 4096 + j * 64;
#pragma unroll
        for (int c = 0; c < 4; c++)
            orow[colg + 16 * c] = hadd2(acc2[e][c]) + bvv[c];
    }
}

// ===========================================================================
// Launch
// ===========================================================================
extern "C" void kernel_launch(void* const* d_in, const int* in_sizes, int n_in,
                              void* d_out, int out_size)
{
    (void)in_sizes; (void)n_in; (void)out_size;

    const float* x    = (const float*)d_in[0];
    Ptr6 us, vs;
    for (int l = 0; l < 6; l++) {
        us.p[l] = (const float*)d_in[1 + 2 * l];
        vs.p[l] = (const float*)d_in[2 + 2 * l];
    }
    const float* ds   = (const float*)d_in[13];
    const float* bias = (const float*)d_in[14];
    float* out        = (float*)d_out;

    const int SMEM2 = (64 * 164 + 80 * 128) * (int)sizeof(float);  // 82944 B
    cudaFuncSetAttribute(hodlr_expand_kernel,
                         cudaFuncAttributeMaxDynamicSharedMemorySize, SMEM2);

    repack_us_kernel<<<96, 256>>>(us);
    repack_ds_kernel<<<16, 256>>>(ds);
    repack_vs_kernel<<<768, 256>>>(vs);
    hodlr_proj_kernel<<<256, NTHREADS>>>(x);
    hodlr_expand_kernel<<<dim3(64, 256), NTHREADS, SMEM2>>>(x, bias, out);
}

// round 11
// speedup vs baseline: 2.4929x; 1.9985x over previous
#include <cuda_runtime.h>
#include <cstdint>

// ---------------------------------------------------------------------------
// HODLR linear on TF32 tensor cores (mma.sync.m16n8k8.tf32).
//
//   repack:  us -> g_Wp [kc][64][96]   (tf32-rounded, chunk-major)
//            ds -> g_Dr (rounded, same layout), vs -> g_Vr (rounded)
//   proj:    per 64-k chunk GEMM X(128x64)@U(64x96); mma C fragments are the
//            HODLR accumulators, flushed (tf32-rounded) to g_T at block ends.
//   expand:  per (output block j, 128-token tile): K=160 GEMM
//            A=[x_j | T slices], B=[ds_j ; vs slices], + bias -> out.
//
// Smem banking: A tiles row-stride = 68/164 (== 4 mod 32)  -> A frags clean.
//               B tiles row-stride = 104/72 (== 8 mod 32)  -> B frags clean.
// ---------------------------------------------------------------------------

#define NT 256

__device__ __align__(16) float g_T [16384ull * 2048];
__device__ __align__(16) float g_Wp[64 * 6144];    // [kc][k_local(64)][96]
__device__ __align__(16) float g_Dr[64 * 4096];    // rounded ds, same layout
__device__ __align__(16) float g_Vr[6 * 65536];    // rounded vs, same layout

struct Ptr6 { const float* p[6]; };

__host__ __device__ __forceinline__ int t_off(int l) {
    const int offs[6] = {0, 32, 96, 224, 480, 992};
    return offs[l];
}

__device__ __forceinline__ uint32_t cvt_tf32(float f) {
    uint32_t u; asm("cvt.rna.tf32.f32 %0, %1;" : "=r"(u) : "f"(f)); return u;
}
__device__ __forceinline__ float round_tf32(float f) {
    uint32_t u; asm("cvt.rna.tf32.f32 %0, %1;" : "=r"(u) : "f"(f));
    return __uint_as_float(u);
}
__device__ __forceinline__ void mma_tf32(float c[4], const uint32_t a[4],
                                         uint32_t b0, uint32_t b1) {
    asm("mma.sync.aligned.m16n8k8.row.col.f32.tf32.tf32.f32 "
        "{%0,%1,%2,%3}, {%4,%5,%6,%7}, {%8,%9}, {%0,%1,%2,%3};"
        : "+f"(c[0]), "+f"(c[1]), "+f"(c[2]), "+f"(c[3])
        : "r"(a[0]), "r"(a[1]), "r"(a[2]), "r"(a[3]), "r"(b0), "r"(b1));
}
__device__ __forceinline__ uint32_t smem_u32(const void* p) {
    return (uint32_t)__cvta_generic_to_shared(p);
}
__device__ __forceinline__ void cpa(uint32_t d, const float* s) {
    asm volatile("cp.async.cg.shared.global [%0], [%1], 16;" :: "r"(d), "l"(s));
}
#define CP_COMMIT  asm volatile("cp.async.commit_group;")
#define CP_WAIT(n) asm volatile("cp.async.wait_group %0;" :: "n"(n))

// ===========================================================================
// Repack kernels: tf32-round weights (and chunk-major re-layout for us).
// ===========================================================================
__global__ void repack_us_k(Ptr6 us) {
    const int i = blockIdx.x * blockDim.x + threadIdx.x;   // 24576
    if (i >= 24576) return;
    const int l = i >> 12, k = i & 4095;
    const int kc = k >> 6, kl = k & 63;
    const float* s = us.p[l] + (size_t)k * 16;
    float* d = g_Wp + kc * 6144 + kl * 96 + l * 16;
#pragma unroll
    for (int r = 0; r < 16; r++) d[r] = round_tf32(s[r]);
}
__global__ void repack_ds_k(const float* __restrict__ ds) {
    const int i = blockIdx.x * blockDim.x + threadIdx.x;   // 4096 rows
    if (i >= 4096) return;
    const float* s = ds + (size_t)i * 64;
    float* d = g_Dr + (size_t)i * 64;
#pragma unroll
    for (int c = 0; c < 64; c++) d[c] = round_tf32(s[c]);
}
__global__ void repack_vs_k(Ptr6 vs) {
    const int i = blockIdx.x * blockDim.x + threadIdx.x;   // 24576
    if (i >= 24576) return;
    const int l = i >> 12, e = i & 4095;
    const float* s = vs.p[l] + (size_t)e * 16;
    float* d = g_Vr + l * 65536 + (size_t)e * 16;
#pragma unroll
    for (int r = 0; r < 16; r++) d[r] = round_tf32(s[r]);
}

// ===========================================================================
// Proj: grid 128 CTAs x 256 thr, CTA = 128 tokens, N=96 (6 layers x rank16).
// Warp (mg = wid>>1, ng = wid&1): rows mg*32 (2 m16), cols ng*48 (6 n8).
// Double-buffered cp.async staging. Flush C frags at block boundaries.
// ===========================================================================
__global__ __launch_bounds__(NT) void proj_k(const float* __restrict__ x)
{
    extern __shared__ float sm[];
    const int XS = 128 * 68, WS = 64 * 104, BUF = XS + WS;

    const int tid = threadIdx.x, wid = tid >> 5, lane = tid & 31;
    const int tid4 = lane >> 2, tc = lane & 3;
    const int mg = wid >> 1, ng = wid & 1;
    const int tok0 = blockIdx.x * 128;

    float c[2][6][4];
#pragma unroll
    for (int mi = 0; mi < 2; mi++)
#pragma unroll
        for (int nt = 0; nt < 6; nt++)
#pragma unroll
            for (int q = 0; q < 4; q++) c[mi][nt][q] = 0.f;

    auto stage = [&](int buf, int kc) {
        float* xs = sm + buf * BUF;
        float* ws = xs + XS;
        const uint32_t xsa = smem_u32(xs), wsa = smem_u32(ws);
#pragma unroll
        for (int p = 0; p < 8; p++) {                 // x: 2048 float4
            const int idx = p * NT + tid, row = idx >> 4, f4 = idx & 15;
            cpa(xsa + (row * 68 + f4 * 4) * 4,
                x + (size_t)(tok0 + row) * 4096 + kc * 64 + f4 * 4);
        }
#pragma unroll
        for (int p = 0; p < 6; p++) {                 // w: 1536 float4
            const int idx = p * NT + tid, k = idx / 24, f4 = idx % 24;
            cpa(wsa + (k * 104 + f4 * 4) * 4,
                g_Wp + kc * 6144 + k * 96 + f4 * 4);
        }
        CP_COMMIT;
    };

    auto compute = [&](int buf) {
        const float* xs = sm + buf * BUF;
        const float* ws = xs + XS;
#pragma unroll
        for (int ks = 0; ks < 8; ks++) {
            uint32_t a[2][4];
#pragma unroll
            for (int mi = 0; mi < 2; mi++) {
                const float* ab = xs + (mg * 32 + mi * 16 + tid4) * 68 + ks * 8 + tc;
                a[mi][0] = cvt_tf32(ab[0]);
                a[mi][1] = cvt_tf32(ab[8 * 68]);
                a[mi][2] = cvt_tf32(ab[4]);
                a[mi][3] = cvt_tf32(ab[8 * 68 + 4]);
            }
#pragma unroll
            for (int nt = 0; nt < 6; nt++) {
                const float* bb = ws + (ks * 8 + tc) * 104 + ng * 48 + nt * 8 + tid4;
                const uint32_t b0 = __float_as_uint(bb[0]);
                const uint32_t b1 = __float_as_uint(bb[4 * 104]);
                mma_tf32(c[0][nt], a[0], b0, b1);
                mma_tf32(c[1][nt], a[1], b0, b1);
            }
        }
    };

    stage(0, 0);
    stage(1, 1);

    for (int kc = 0; kc < 64; kc++) {
        CP_WAIT(1);
        __syncthreads();
        compute(kc & 1);
        __syncthreads();
        if (kc + 2 < 64) stage(kc & 1, kc + 2);

        // flush layers whose block ends at this chunk (warp ng owns 3 layers)
#pragma unroll
        for (int lloc = 0; lloc < 3; lloc++) {
            const int l = 3 * ng + lloc;
            const int shift = 5 - l;
            if (((kc + 1) & ((1 << shift) - 1)) == 0) {
                const int b = kc >> shift;
#pragma unroll
                for (int mi = 0; mi < 2; mi++)
#pragma unroll
                    for (int u = 0; u < 2; u++) {
                        float* fr = c[mi][2 * lloc + u];
                        const size_t tok = tok0 + mg * 32 + mi * 16 + tid4;
                        float* base = g_T + tok * 2048 + t_off(l)
                                    + b * 16 + 8 * u + 2 * tc;
                        *reinterpret_cast<float2*>(base) =
                            make_float2(round_tf32(fr[0]), round_tf32(fr[1]));
                        *reinterpret_cast<float2*>(base + 8 * 2048) =
                            make_float2(round_tf32(fr[2]), round_tf32(fr[3]));
                        fr[0] = fr[1] = fr[2] = fr[3] = 0.f;
                    }
            }
        }
    }
}

// ===========================================================================
// Expand: grid (64 j, 128 token tiles) x 256 thr. CTA: M=128, N=64, K=160.
// Warp (mg = wid>>1, ng = wid&1): rows mg*32 (2 m16), cols ng*32 (4 n8).
// ===========================================================================
__global__ __launch_bounds__(NT) void expand_k(
    const float* __restrict__ x, const float* __restrict__ bias,
    float* __restrict__ out)
{
    extern __shared__ float sm[];
    float* as = sm;               // [128][164] : cols 0..63 x, 64..159 T
    float* bs = sm + 128 * 164;   // [160][72]  : rows 0..63 ds, 64..159 vs

    const int tid = threadIdx.x, wid = tid >> 5, lane = tid & 31;
    const int tid4 = lane >> 2, tc = lane & 3;
    const int mg = wid >> 1, ng = wid & 1;
    const int j = blockIdx.x, tok0 = blockIdx.y * 128;

    int pb[6], lo[6];
#pragma unroll
    for (int l = 0; l < 6; l++) {
        const int shift = 5 - l;
        pb[l] = (j >> shift) ^ 1;
        lo[l] = (j & ((1 << shift) - 1)) * 64;
    }

    const uint32_t asa = smem_u32(as), bsa = smem_u32(bs);
#pragma unroll
    for (int p = 0; p < 8; p++) {                     // x block j
        const int idx = p * NT + tid, row = idx >> 4, f4 = idx & 15;
        cpa(asa + (row * 164 + f4 * 4) * 4,
            x + (size_t)(tok0 + row) * 4096 + j * 64 + f4 * 4);
    }
#pragma unroll
    for (int p = 0; p < 12; p++) {                    // T slices (128 x 24 f4)
        const int idx = p * NT + tid, tok = idx / 24, c4 = idx % 24;
        const int cc = c4 * 4, l = cc >> 4, r = cc & 15;
        cpa(asa + (tok * 164 + 64 + cc) * 4,
            g_T + (size_t)(tok0 + tok) * 2048 + t_off(l) + pb[l] * 16 + r);
    }
#pragma unroll
    for (int p = 0; p < 4; p++) {                     // ds rows 0..63
        const int idx = p * NT + tid, k = idx >> 4, f4 = idx & 15;
        cpa(bsa + (k * 72 + f4 * 4) * 4, g_Dr + j * 4096 + k * 64 + f4 * 4);
    }
#pragma unroll
    for (int p = 0; p < 6; p++) {                     // vs rows 64..159
        const int idx = p * NT + tid, rr = idx >> 4, f4 = idx & 15;
        const int l = rr >> 4, r = rr & 15;
        cpa(bsa + ((64 + rr) * 72 + f4 * 4) * 4,
            g_Vr + l * 65536 + (size_t)(pb[l] * 16 + r) * (1 << (11 - l))
                 + lo[l] + f4 * 4);
    }
    CP_COMMIT;
    CP_WAIT(0);
    __syncthreads();

    float c[2][4][4];
#pragma unroll
    for (int mi = 0; mi < 2; mi++)
#pragma unroll
        for (int nt = 0; nt < 4; nt++)
#pragma unroll
            for (int q = 0; q < 4; q++) c[mi][nt][q] = 0.f;

#pragma unroll 4
    for (int ks = 0; ks < 20; ks++) {
        uint32_t a[2][4];
#pragma unroll
        for (int mi = 0; mi < 2; mi++) {
            const float* ab = as + (mg * 32 + mi * 16 + tid4) * 164 + ks * 8 + tc;
            a[mi][0] = cvt_tf32(ab[0]);
            a[mi][1] = cvt_tf32(ab[8 * 164]);
            a[mi][2] = cvt_tf32(ab[4]);
            a[mi][3] = cvt_tf32(ab[8 * 164 + 4]);
        }
#pragma unroll
        for (int nt = 0; nt < 4; nt++) {
            const float* bb = bs + (ks * 8 + tc) * 72 + ng * 32 + nt * 8 + tid4;
            const uint32_t b0 = __float_as_uint(bb[0]);
            const uint32_t b1 = __float_as_uint(bb[4 * 72]);
            mma_tf32(c[0][nt], a[0], b0, b1);
            mma_tf32(c[1][nt], a[1], b0, b1);
        }
    }

    // epilogue: bias + paired stores (cols 2tc, 2tc+1 contiguous)
#pragma unroll
    for (int nt = 0; nt < 4; nt++) {
        const int col = j * 64 + ng * 32 + nt * 8 + 2 * tc;
        const float2 bv = *reinterpret_cast<const float2*>(bias + col);
#pragma unroll
        for (int mi = 0; mi < 2; mi++) {
            const size_t row = tok0 + mg * 32 + mi * 16 + tid4;
            float2 o0, o1;
            o0.x = c[mi][nt][0] + bv.x;  o0.y = c[mi][nt][1] + bv.y;
            o1.x = c[mi][nt][2] + bv.x;  o1.y = c[mi][nt][3] + bv.y;
            *reinterpret_cast<float2*>(out + row * 4096 + col) = o0;
            *reinterpret_cast<float2*>(out + (row + 8) * 4096 + col) = o1;
        }
    }
}

// ===========================================================================
// Launch
// ===========================================================================
extern "C" void kernel_launch(void* const* d_in, const int* in_sizes, int n_in,
                              void* d_out, int out_size)
{
    (void)in_sizes; (void)n_in; (void)out_size;

    const float* x = (const float*)d_in[0];
    Ptr6 us, vs;
    for (int l = 0; l < 6; l++) {
        us.p[l] = (const float*)d_in[1 + 2 * l];
        vs.p[l] = (const float*)d_in[2 + 2 * l];
    }
    const float* ds   = (const float*)d_in[13];
    const float* bias = (const float*)d_in[14];
    float* out        = (float*)d_out;

    const int SMEM_P = 2 * (128 * 68 + 64 * 104) * (int)sizeof(float); // 122880
    const int SMEM_E = (128 * 164 + 160 * 72) * (int)sizeof(float);    // 130048
    cudaFuncSetAttribute(proj_k,
                         cudaFuncAttributeMaxDynamicSharedMemorySize, SMEM_P);
    cudaFuncSetAttribute(expand_k,
                         cudaFuncAttributeMaxDynamicSharedMemorySize, SMEM_E);

    repack_us_k<<<96, 256>>>(us);
    repack_ds_k<<<16, 256>>>(ds);
    repack_vs_k<<<96, 256>>>(vs);
    proj_k<<<128, NT, SMEM_P>>>(x);
    expand_k<<<dim3(64, 128), NT, SMEM_E>>>(x, bias, out);
}